// round 5
// baseline (speedup 1.0000x reference)
#include <cuda_runtime.h>

// DifferentiableBundleAdjustment: B=4096 rows, each a serial 512-step scan on
// 7-float state. out[b,s,0:7] = state, out[b,s,7:15] = 0.
// One thread per row; 128 warps chip-wide -> issue-bound, so everything is
// fused into one kernel (no separate zero-fill) with vectorized stores and a
// double-buffered load pipeline.

constexpr int B_DIM = 4096;
constexpr int S_DIM = 512;
constexpr int PD    = 32;   // dba_params last dim
constexpr int SD    = 15;   // state dim / output last dim
constexpr int UB    = 8;    // steps per pipeline body
constexpr int NBODY = S_DIM / UB;  // 64

// Store one output row (15 floats: 7 state + 8 zeros) at float* o, where the
// byte offset of o from a 16B-aligned base is 60*s. ph = s & 3 selects the
// alignment phase: 60*s mod 16 = {0,12,8,4} for ph {0,1,2,3}. ph is a
// compile-time constant after full unroll, so the branches fold away.
__device__ __forceinline__ void store_row(float* o, int ph,
                                          float p0, float p1, float p2,
                                          float q0, float q1, float q2, float q3)
{
    const float4 z4 = make_float4(0.f, 0.f, 0.f, 0.f);
    const float2 z2 = make_float2(0.f, 0.f);
    if (ph == 0) {                      // o = 16k + 0
        *reinterpret_cast<float4*>(o + 0)  = make_float4(p0, p1, p2, q0);
        *reinterpret_cast<float2*>(o + 4)  = make_float2(q1, q2);
        o[6] = q3; o[7] = 0.f;
        *reinterpret_cast<float4*>(o + 8)  = z4;
        *reinterpret_cast<float2*>(o + 12) = z2;
        o[14] = 0.f;
    } else if (ph == 1) {               // o = 16k + 12
        o[0] = p0;
        *reinterpret_cast<float4*>(o + 1)  = make_float4(p1, p2, q0, q1);
        *reinterpret_cast<float2*>(o + 5)  = make_float2(q2, q3);
        *reinterpret_cast<float2*>(o + 7)  = z2;
        *reinterpret_cast<float4*>(o + 9)  = z4;
        *reinterpret_cast<float2*>(o + 13) = z2;
    } else if (ph == 2) {               // o = 16k + 8
        *reinterpret_cast<float2*>(o + 0)  = make_float2(p0, p1);
        *reinterpret_cast<float4*>(o + 2)  = make_float4(p2, q0, q1, q2);
        o[6] = q3; o[7] = 0.f;
        *reinterpret_cast<float2*>(o + 8)  = z2;
        *reinterpret_cast<float4*>(o + 10) = z4;
        o[14] = 0.f;
    } else {                            // o = 16k + 4
        o[0] = p0;
        *reinterpret_cast<float2*>(o + 1)  = make_float2(p1, p2);
        *reinterpret_cast<float4*>(o + 3)  = make_float4(q0, q1, q2, q3);
        *reinterpret_cast<float4*>(o + 7)  = z4;
        *reinterpret_cast<float4*>(o + 11) = z4;
    }
}

// Load one 8-step body of deltas (first 8 floats of each 128B dba row).
#define LOADBODY(BUF, body)                                                    \
    {                                                                          \
        const float4* __restrict__ src =                                       \
            reinterpret_cast<const float4*>(dp + (size_t)(body) * UB * PD);    \
        _Pragma("unroll")                                                      \
        for (int j = 0; j < UB; j++) {                                         \
            BUF[j][0] = src[j * 8 + 0];                                        \
            BUF[j][1] = src[j * 8 + 1];                                        \
        }                                                                      \
    }

// Process one 8-step body: emit current state, then advance with delta.
#define PROCESS(BUF)                                                           \
    {                                                                          \
        _Pragma("unroll")                                                      \
        for (int j = 0; j < UB; j++) {                                         \
            store_row(o, j & 3, p0, p1, p2, q0, q1, q2, q3);                   \
            o += SD;                                                           \
            float4 da = BUF[j][0];                                             \
            float4 db = BUF[j][1];                                             \
            p0 = fmaf(0.1f, da.x, p0);                                         \
            p1 = fmaf(0.1f, da.y, p1);                                         \
            p2 = fmaf(0.1f, da.z, p2);                                         \
            float u0 = fmaf(0.1f, da.w, q0);                                   \
            float u1 = fmaf(0.1f, db.x, q1);                                   \
            float u2 = fmaf(0.1f, db.y, q2);                                   \
            float u3 = fmaf(0.1f, db.z, q3);                                   \
            float nrm = fmaf(u0, u0, u1 * u1) + fmaf(u2, u2, u3 * u3);         \
            float r = rsqrtf(nrm);                                             \
            q0 = u0 * r; q1 = u1 * r; q2 = u2 * r; q3 = u3 * r;                \
        }                                                                      \
    }

__global__ void __launch_bounds__(32, 1)
dba_scan_kernel(const float* __restrict__ dba,
                const float* __restrict__ gt,
                float* __restrict__ out)
{
    int b = blockIdx.x * 32 + threadIdx.x;
    if (b >= B_DIM) return;

    const float* __restrict__ dp = dba + (size_t)b * S_DIM * PD;
    const float* __restrict__ g  = gt  + (size_t)b * S_DIM * SD;   // row s=0
    float*       __restrict__ o  = out + (size_t)b * S_DIM * SD;

    float p0 = g[0], p1 = g[1], p2 = g[2];
    float q0 = g[3], q1 = g[4], q2 = g[5], q3 = g[6];

    float4 bufA[UB][2];
    float4 bufB[UB][2];

    LOADBODY(bufA, 0);

    #pragma unroll 1
    for (int k = 0; k < NBODY; k += 2) {
        // Prefetch body k+1 while processing body k (gap ~1 body > DRAM lat).
        LOADBODY(bufB, k + 1);
        PROCESS(bufA);
        if (k + 2 < NBODY) {
            LOADBODY(bufA, k + 2);
        }
        PROCESS(bufB);
    }
}

extern "C" void kernel_launch(void* const* d_in, const int* in_sizes, int n_in,
                              void* d_out, int out_size)
{
    const float* dba = (const float*)d_in[0];   // [4096, 512, 32]
    // d_in[1] = imu_measurements: unused by the reference computation
    const float* gt  = (const float*)d_in[2];   // [4096, 512, 15]
    float* out = (float*)d_out;                 // [4096, 512, 15]

    (void)in_sizes; (void)n_in; (void)out_size;

    dba_scan_kernel<<<B_DIM / 32, 32>>>(dba, gt, out);
}

// round 7
// speedup vs baseline: 1.0330x; 1.0330x over previous
#include <cuda_runtime.h>

// DifferentiableBundleAdjustment, round 2 of tuning.
// B=4096 independent rows, each a serial 512-step scan on 7-float state.
// out[b,s,0:7] = state, out[b,s,7:15] = 0.
//
// Layout: 128 blocks x 32 threads; lane = one batch row (in-lane serial chain,
// 36 cyc/step). The R5 kernel was L1tex-wavefront-bound: every STG touched 32
// distinct 128B lines (lanes 64KB apart). Fix: stage 8 steps of output
// (480B/row, exact output layout incl. zeros) in SMEM, then copy out each
// row's 480B chunk coalesced (LDS.128 + STG.128, lanes 0-29, 1 instr pair per
// row). Reads stay strided on purpose: only 32B of each 128B dba row is used;
// coalescing reads would 4x the DRAM read traffic.

constexpr int B_DIM = 4096;
constexpr int S_DIM = 512;
constexpr int PD    = 32;   // dba_params last dim
constexpr int SD    = 15;   // output last dim
constexpr int UB    = 8;    // steps per superstep (480B staged per row)
constexpr int NBODY = S_DIM / UB;  // 64
constexpr int ROWS  = 32;   // rows per warp/block
constexpr int ROW_F = 132;  // smem floats per row: 121 used (8*15+1 spill) + pad;
                            // 132*4=528B: 16B-aligned, bank stride 4 -> phase-clean

// Store one output row (15 floats: 7 state + 8 zeros) at float* o, where the
// byte offset of o from a 16B-aligned base is 60*j. ph = j & 3 selects the
// alignment phase: 60*j mod 16 = {0,12,8,4}. Works for gmem or smem pointers.
// NOTE (ph==1/ph==2 smem use): writes only within [0,15); ph-phase vector ops
// never cross the 15-float row end except the benign 16th float at offsets
// that the NEXT step overwrites (same thread, program order) or pad covers.
__device__ __forceinline__ void store_row(float* o, int ph,
                                          float p0, float p1, float p2,
                                          float q0, float q1, float q2, float q3)
{
    const float4 z4 = make_float4(0.f, 0.f, 0.f, 0.f);
    const float2 z2 = make_float2(0.f, 0.f);
    if (ph == 0) {                      // base + 0
        *reinterpret_cast<float4*>(o + 0)  = make_float4(p0, p1, p2, q0);
        *reinterpret_cast<float2*>(o + 4)  = make_float2(q1, q2);
        o[6] = q3; o[7] = 0.f;
        *reinterpret_cast<float4*>(o + 8)  = z4;
        *reinterpret_cast<float2*>(o + 12) = z2;
        o[14] = 0.f;
    } else if (ph == 1) {               // base + 12 mod 16
        o[0] = p0;
        *reinterpret_cast<float4*>(o + 1)  = make_float4(p1, p2, q0, q1);
        *reinterpret_cast<float2*>(o + 5)  = make_float2(q2, q3);
        *reinterpret_cast<float2*>(o + 7)  = z2;
        *reinterpret_cast<float4*>(o + 9)  = z4;
        *reinterpret_cast<float2*>(o + 13) = z2;
    } else if (ph == 2) {               // base + 8 mod 16
        *reinterpret_cast<float2*>(o + 0)  = make_float2(p0, p1);
        *reinterpret_cast<float4*>(o + 2)  = make_float4(p2, q0, q1, q2);
        o[6] = q3; o[7] = 0.f;
        *reinterpret_cast<float2*>(o + 8)  = z2;
        *reinterpret_cast<float4*>(o + 10) = z4;
        o[14] = 0.f;
    } else {                            // base + 4 mod 16
        o[0] = p0;
        *reinterpret_cast<float2*>(o + 1)  = make_float2(p1, p2);
        *reinterpret_cast<float4*>(o + 3)  = make_float4(q0, q1, q2, q3);
        *reinterpret_cast<float4*>(o + 7)  = z4;
        *reinterpret_cast<float4*>(o + 11) = z4;
    }
}

// Load one 8-step body of deltas (first 8 floats of each 128B dba row).
#define LOADBODY(BUF, body)                                                    \
    {                                                                          \
        const float4* __restrict__ src =                                       \
            reinterpret_cast<const float4*>(dp + (size_t)(body) * UB * PD);    \
        _Pragma("unroll")                                                      \
        for (int j = 0; j < UB; j++) {                                         \
            BUF[j][0] = src[j * 8 + 0];                                        \
            BUF[j][1] = src[j * 8 + 1];                                        \
        }                                                                      \
    }

// Process one 8-step body: stage current state row into smem, then advance.
#define PROCESS(BUF)                                                           \
    {                                                                          \
        _Pragma("unroll")                                                      \
        for (int j = 0; j < UB; j++) {                                         \
            store_row(srow + j * SD, j & 3, p0, p1, p2, q0, q1, q2, q3);       \
            float4 da = BUF[j][0];                                             \
            float4 db = BUF[j][1];                                             \
            p0 = fmaf(0.1f, da.x, p0);                                         \
            p1 = fmaf(0.1f, da.y, p1);                                         \
            p2 = fmaf(0.1f, da.z, p2);                                         \
            float u0 = fmaf(0.1f, da.w, q0);                                   \
            float u1 = fmaf(0.1f, db.x, q1);                                   \
            float u2 = fmaf(0.1f, db.y, q2);                                   \
            float u3 = fmaf(0.1f, db.z, q3);                                   \
            float nrm = fmaf(u0, u0, u1 * u1) + fmaf(u2, u2, u3 * u3);         \
            float r = rsqrtf(nrm);                                             \
            q0 = u0 * r; q1 = u1 * r; q2 = u2 * r; q3 = u3 * r;                \
        }                                                                      \
    }

// Coalesced copy-out: 32 rows x 480B from smem stage to gmem.
// Lanes 0-29 each move 16B per row; gmem span per row = 480B contiguous.
#define COPYOUT(k)                                                             \
    if (cactive) {                                                             \
        float* od = ob + (size_t)(k) * (UB * SD);                              \
        _Pragma("unroll")                                                      \
        for (int r = 0; r < ROWS; r++) {                                       \
            float4 v = *reinterpret_cast<const float4*>(stage + r * ROW_F + cofs); \
            *reinterpret_cast<float4*>(od + (size_t)r * S_DIM * SD + cofs) = v;    \
        }                                                                      \
    }

__global__ void __launch_bounds__(32, 1)
dba_scan_kernel(const float* __restrict__ dba,
                const float* __restrict__ gt,
                float* __restrict__ out)
{
    __shared__ float stage[ROWS * ROW_F];   // 16896 B

    const int lane = threadIdx.x;
    const int b    = blockIdx.x * ROWS + lane;

    const float* __restrict__ dp = dba + (size_t)b * S_DIM * PD;
    const float* __restrict__ g  = gt  + (size_t)b * S_DIM * SD;   // row s=0
    float* __restrict__ srow     = stage + lane * ROW_F;

    // Copy-out lane role: lanes 0-29 move floats [4*lane, 4*lane+3] of each
    // row's 120-float (8-step) chunk.
    const bool cactive = (lane < 30);
    const int  cofs    = 4 * lane;
    float* __restrict__ ob = out + (size_t)blockIdx.x * ROWS * S_DIM * SD;

    // Initial state (g[0..6]; g[7] read harmlessly, row has 15 floats).
    float4 ga = *reinterpret_cast<const float4*>(g + 0);
    float4 gb = *reinterpret_cast<const float4*>(g + 4);
    float p0 = ga.x, p1 = ga.y, p2 = ga.z;
    float q0 = ga.w, q1 = gb.x, q2 = gb.y, q3 = gb.z;

    float4 bufA[UB][2];
    float4 bufB[UB][2];

    LOADBODY(bufA, 0);

    #pragma unroll 1
    for (int k = 0; k < NBODY; k += 2) {
        LOADBODY(bufB, k + 1);            // prefetch next body while chaining
        PROCESS(bufA);
        __syncwarp();                     // STS visible to copy lanes
        COPYOUT(k);
        __syncwarp();                     // copy done before next STS
        if (k + 2 < NBODY) {
            LOADBODY(bufA, k + 2);
        }
        PROCESS(bufB);
        __syncwarp();
        COPYOUT(k + 1);
        __syncwarp();
    }
}

extern "C" void kernel_launch(void* const* d_in, const int* in_sizes, int n_in,
                              void* d_out, int out_size)
{
    const float* dba = (const float*)d_in[0];   // [4096, 512, 32]
    // d_in[1] = imu_measurements: unused by the reference computation
    const float* gt  = (const float*)d_in[2];   // [4096, 512, 15]
    float* out = (float*)d_out;                 // [4096, 512, 15]

    (void)in_sizes; (void)n_in; (void)out_size;

    dba_scan_kernel<<<B_DIM / ROWS, ROWS>>>(dba, gt, out);
}

// round 12
// speedup vs baseline: 1.6065x; 1.5553x over previous
#include <cuda_runtime.h>
#include <cstdint>
#include <cstddef>

// DifferentiableBundleAdjustment, round 3 of tuning (resubmit; R8-R11 never ran).
// R7 evidence: dur = DRAM_traffic / achieved_BW = 366MB / 3.4TB/s. Two broken
// factors: (1) ~180MB surplus traffic (register spills at regs=255 and/or
// full-line L2 fetch of 32B-sector reads), (2) BW capped by in-flight bytes
// (2MB chip-wide from the shallow register double-buffer).
// This round: deep cp.async ring (8 stages, 7-body lead) in dynamic SMEM.
// - no register buffers -> no spills
// - 3.5x more outstanding reads -> higher achieved BW
// - cp.async lane mapping: each instr covers 2 rows (16 lines vs 32)
// - output zeros pre-filled once; per step only 7 floats stored (3 STS)

constexpr int B_DIM = 4096;
constexpr int S_DIM = 512;
constexpr int PD    = 32;   // dba_params last dim
constexpr int SD    = 15;   // output last dim
constexpr int UB    = 8;    // steps per body
constexpr int NBODY = S_DIM / UB;   // 64
constexpr int ROWS  = 32;   // batch rows per block (= lanes)
constexpr int RING  = 8;    // cp.async ring depth (power of 2)
constexpr int DROW  = 68;   // floats per row per delta stage (64 data + 4 pad; 272B, 16B-aligned)
constexpr int DSTAGE = ROWS * DROW;          // 2176 floats per stage
constexpr int ROW_F  = 132; // out-stage floats per row (528B, 16B-aligned)
constexpr int SMEM_FLOATS = RING * DSTAGE + ROWS * ROW_F;  // 17408 + 4224
constexpr int SMEM_BYTES  = SMEM_FLOATS * 4;               // 86528 B

__device__ __forceinline__ void cpa16(uint32_t dst, const float* src) {
    asm volatile("cp.async.cg.shared.global [%0], [%1], 16;\n"
                 :: "r"(dst), "l"(src));
}
#define CPA_COMMIT() asm volatile("cp.async.commit_group;\n" ::: "memory")
#define CPA_WAIT7()  asm volatile("cp.async.wait_group 7;\n" ::: "memory")

// Issue one body's deltas into ring stage (kb % RING).
// Tasks per body: 32 rows x 8 steps x 2 halves of 16B (only first 32B of each
// 128B dba row). Instr i: lanes 0-15 -> row 2i, lanes 16-31 -> row 2i+1;
// piece p = 2*j + h. Each instr touches 16 gmem lines (2 rows' chunks).
// SMEM dst packs the 32B/step contiguously: row base + p*16B.
#define ISSUE(kb)                                                              \
    {                                                                          \
        const int half  = lane >> 4;                                           \
        const int piece = lane & 15;                                           \
        uint32_t dstage = sbase + (uint32_t)(((kb) & (RING - 1)) * (DSTAGE * 4)); \
        const float* srcb = dba_blk + (size_t)(kb) * (UB * PD);                \
        _Pragma("unroll")                                                      \
        for (int i = 0; i < 16; i++) {                                         \
            int r = 2 * i + half;                                              \
            cpa16(dstage + (uint32_t)(r * (DROW * 4) + piece * 16),            \
                  srcb + (size_t)r * (S_DIM * PD)                              \
                       + (piece >> 1) * PD + (piece & 1) * 4);                 \
        }                                                                      \
    }

// Store the 7 state floats at float-offset o = 15*j from the 16B-aligned row
// base; ph = (3*j) & 3 = o % 4. Never touches the pre-zeroed tail [o+7, o+15).
__device__ __forceinline__ void put7(float* o, int ph,
                                     float p0, float p1, float p2,
                                     float q0, float q1, float q2, float q3)
{
    if (ph == 0) {
        *reinterpret_cast<float4*>(o + 0) = make_float4(p0, p1, p2, q0);
        *reinterpret_cast<float2*>(o + 4) = make_float2(q1, q2);
        o[6] = q3;
    } else if (ph == 1) {
        o[0] = p0;
        *reinterpret_cast<float2*>(o + 1) = make_float2(p1, p2);
        *reinterpret_cast<float4*>(o + 3) = make_float4(q0, q1, q2, q3);
    } else if (ph == 2) {
        *reinterpret_cast<float2*>(o + 0) = make_float2(p0, p1);
        *reinterpret_cast<float4*>(o + 2) = make_float4(p2, q0, q1, q2);
        o[6] = q3;
    } else {
        o[0] = p0;
        *reinterpret_cast<float4*>(o + 1) = make_float4(p1, p2, q0, q1);
        *reinterpret_cast<float2*>(o + 5) = make_float2(q2, q3);
    }
}

// Coalesced copy-out: 32 rows x 480B (8 steps x 15 floats incl. zeros) from
// the out stage to gmem. Lanes 0-29 move 16B per row; both sides 16B-aligned.
#define COPYOUT(k)                                                             \
    if (lane < 30) {                                                           \
        float* od = ob + (size_t)(k) * (UB * SD);                              \
        const int cofs = 4 * lane;                                             \
        _Pragma("unroll")                                                      \
        for (int r = 0; r < ROWS; r++) {                                       \
            float4 v = *reinterpret_cast<const float4*>(ostage + r * ROW_F + cofs); \
            *reinterpret_cast<float4*>(od + (size_t)r * (S_DIM * SD) + cofs) = v;   \
        }                                                                      \
    }

__global__ void __launch_bounds__(32, 1)
dba_scan_kernel(const float* __restrict__ dba,
                const float* __restrict__ gt,
                float* __restrict__ out)
{
    extern __shared__ float smem[];
    float* dring  = smem;                    // RING * DSTAGE floats
    float* ostage = smem + RING * DSTAGE;    // ROWS * ROW_F floats

    const int lane = threadIdx.x;
    const int b    = blockIdx.x * ROWS + lane;

    const float* __restrict__ dba_blk =
        dba + (size_t)blockIdx.x * ROWS * S_DIM * PD;
    const float* __restrict__ g = gt + (size_t)b * S_DIM * SD;   // row s=0
    float* __restrict__ ob = out + (size_t)blockIdx.x * ROWS * S_DIM * SD;

    const uint32_t sbase = (uint32_t)__cvta_generic_to_shared(dring);

    // Zero-prefill the out stage once; the zero tail of each 15-float row is
    // never overwritten afterwards (put7 writes only 7 floats).
    for (int i = lane; i < ROWS * ROW_F; i += 32) ostage[i] = 0.f;

    // Initial state from gt[:,0,0:7] (g 16B-aligned: b*15*512*4 % 16 == 0).
    float4 ga = *reinterpret_cast<const float4*>(g + 0);
    float4 gb = *reinterpret_cast<const float4*>(g + 4);
    float p0 = ga.x, p1 = ga.y, p2 = ga.z;
    float q0 = ga.w, q1 = gb.x, q2 = gb.y, q3 = gb.z;

    // Prologue: issue bodies 0..RING-2 (7 groups in flight).
    #pragma unroll 1
    for (int s = 0; s < RING - 1; s++) {
        ISSUE(s);
        CPA_COMMIT();
    }
    __syncwarp();   // ostage zero-fill visible to copy lanes

    float* const srow = ostage + lane * ROW_F;

    #pragma unroll 1
    for (int k = 0; k < NBODY; k++) {
        // Keep the pipeline full: issue body k+RING-1 (empty group near the
        // end keeps the pending count constant so wait_group(7) always
        // completes exactly body k).
        int kb = k + RING - 1;
        if (kb < NBODY) { ISSUE(kb); }
        CPA_COMMIT();
        CPA_WAIT7();
        __syncwarp();   // cross-lane visibility of this stage's cp.async data

        const float* drow = dring + (k & (RING - 1)) * DSTAGE + lane * DROW;

        #pragma unroll
        for (int j = 0; j < UB; j++) {
            put7(srow + j * SD, (3 * j) & 3, p0, p1, p2, q0, q1, q2, q3);
            float4 da = *reinterpret_cast<const float4*>(drow + j * 8);
            float4 db = *reinterpret_cast<const float4*>(drow + j * 8 + 4);
            p0 = fmaf(0.1f, da.x, p0);
            p1 = fmaf(0.1f, da.y, p1);
            p2 = fmaf(0.1f, da.z, p2);
            float u0 = fmaf(0.1f, da.w, q0);
            float u1 = fmaf(0.1f, db.x, q1);
            float u2 = fmaf(0.1f, db.y, q2);
            float u3 = fmaf(0.1f, db.z, q3);
            float nrm = fmaf(u0, u0, u1 * u1) + fmaf(u2, u2, u3 * u3);
            float r = rsqrtf(nrm);
            q0 = u0 * r; q1 = u1 * r; q2 = u2 * r; q3 = u3 * r;
        }

        __syncwarp();   // staged state visible to copy lanes
        COPYOUT(k);
        __syncwarp();   // copy done before next body's put7 overwrites stage
    }
}

extern "C" void kernel_launch(void* const* d_in, const int* in_sizes, int n_in,
                              void* d_out, int out_size)
{
    const float* dba = (const float*)d_in[0];   // [4096, 512, 32]
    // d_in[1] = imu_measurements: unused by the reference computation
    const float* gt  = (const float*)d_in[2];   // [4096, 512, 15]
    float* out = (float*)d_out;                 // [4096, 512, 15]

    (void)in_sizes; (void)n_in; (void)out_size;

    // Unconditional (no static guard — harness rule): host-side, idempotent,
    // not a stream op, so graph-capture-safe.
    cudaFuncSetAttribute(dba_scan_kernel,
                         cudaFuncAttributeMaxDynamicSharedMemorySize,
                         SMEM_BYTES);

    dba_scan_kernel<<<B_DIM / ROWS, ROWS, SMEM_BYTES>>>(dba, gt, out);
}